// round 16
// baseline (speedup 1.0000x reference)
#include <cuda_runtime.h>
#include <cuda_fp16.h>
#include <cstdint>

// Problem constants
#define Bn 4
#define Ln 896
#define Dn 2048
#define HQn 32
#define HKVn 8
#define HDn 64
#define TPF 7
#define MROWS (Bn * Ln)      // 3584
#define NKV (HKVn * HDn)     // 512
#define NQKV (Dn + 2 * NKV)  // 3072
#define LOG2E 1.4426950408889634f
#define QSCALE (0.125f * LOG2E)   // folded into Q at the QKV epilogue

// fp16 operand buffers (no allocation allowed -> device globals)
__device__ __half g_xh[MROWS * Dn];                       // x
__device__ __half g_wqkvh[Dn * NQKV];                     // packed weights
__device__ __half g_woh[Dn * Dn];                         // wo
__device__ __half g_qh[MROWS * Dn];                       // rope'd Q (pre-scaled by QSCALE)
__device__ __half g_kth[MROWS * NKV];                     // rope'd K^T [b][kvh][d][L]
__device__ __half g_vh[MROWS * NKV];                      // V
__device__ __half g_ah[MROWS * Dn];                       // attention out
__device__ float2 g_rope[Ln * 32];                        // (cos, sin) per (l, j)

__device__ __forceinline__ uint32_t smem_u32(const void* p) {
    uint32_t a;
    asm("{ .reg .u64 t; cvta.to.shared.u64 t, %1; cvt.u32.u64 %0, t; }"
        : "=r"(a) : "l"(p));
    return a;
}

#define CP_ASYNC16(dst, src) \
    asm volatile("cp.async.cg.shared.global [%0], [%1], 16;" :: "r"(dst), "l"(src))
#define CP_COMMIT() asm volatile("cp.async.commit_group;" ::: "memory")
#define CP_WAIT1()  asm volatile("cp.async.wait_group 1;" ::: "memory")
#define CP_WAIT0()  asm volatile("cp.async.wait_group 0;" ::: "memory")

#define MMA_FP16(cc, a, b0, b1) \
    asm volatile( \
        "mma.sync.aligned.m16n8k16.row.col.f32.f16.f16.f32 " \
        "{%0,%1,%2,%3}, {%4,%5,%6,%7}, {%8,%9}, {%0,%1,%2,%3};" \
        : "+f"((cc)[0]), "+f"((cc)[1]), "+f"((cc)[2]), "+f"((cc)[3]) \
        : "r"((a)[0]), "r"((a)[1]), "r"((a)[2]), "r"((a)[3]), \
          "r"(b0), "r"(b1))

#define LDSM4(r, addr) \
    asm volatile("ldmatrix.sync.aligned.m8n8.x4.shared.b16 {%0,%1,%2,%3}, [%4];" \
        : "=r"((r)[0]), "=r"((r)[1]), "=r"((r)[2]), "=r"((r)[3]) : "r"(addr))
#define LDSM4T(r, addr) \
    asm volatile("ldmatrix.sync.aligned.m8n8.x4.trans.shared.b16 {%0,%1,%2,%3}, [%4];" \
        : "=r"((r)[0]), "=r"((r)[1]), "=r"((r)[2]), "=r"((r)[3]) : "r"(addr))

// Hardware exp2 on two fp16 lanes at once (MUFU pipe).
__device__ __forceinline__ uint32_t ex2h2(uint32_t x) {
    uint32_t r;
    asm("ex2.approx.f16x2 %0, %1;" : "=r"(r) : "r"(x));
    return r;
}

// ---------------------------------------------------------------------------
// Fused convert + rope-table kernel. Convert region processes CVT_REP float4s
// per thread (grid-strided) for memory-level parallelism.
// ---------------------------------------------------------------------------
#define RT    (Ln * 32)
#define XT4   (MROWS * Dn / 4)
#define WQ4   (Dn * Dn / 4)
#define WK4   (Dn * NKV / 4)
#define TOT4  (XT4 + WQ4 + 2 * WK4 + WQ4)
#define CVT_REP 4
#define CVT4S ((TOT4 + CVT_REP - 1) / CVT_REP)
#define CVT_THREADS (RT + CVT4S)

__device__ __forceinline__ void cvt_one(int i,
    const float* __restrict__ x, const float* __restrict__ wq,
    const float* __restrict__ wk, const float* __restrict__ wv,
    const float* __restrict__ wo)
{
    const float* src;
    __half* dst;
    size_t doff;
    if (i < XT4) {
        src = x + (size_t)i * 4;
        dst = g_xh; doff = (size_t)i * 4;
    } else if (i < XT4 + WQ4) {
        int j = i - XT4;
        int r = j / (Dn / 4), c = j - r * (Dn / 4);
        src = wq + ((size_t)r * Dn + c * 4);
        dst = g_wqkvh; doff = (size_t)r * NQKV + c * 4;
    } else if (i < XT4 + WQ4 + WK4) {
        int j = i - XT4 - WQ4;
        int r = j / (NKV / 4), c = j - r * (NKV / 4);
        src = wk + ((size_t)r * NKV + c * 4);
        dst = g_wqkvh; doff = (size_t)r * NQKV + Dn + c * 4;
    } else if (i < XT4 + WQ4 + 2 * WK4) {
        int j = i - XT4 - WQ4 - WK4;
        int r = j / (NKV / 4), c = j - r * (NKV / 4);
        src = wv + ((size_t)r * NKV + c * 4);
        dst = g_wqkvh; doff = (size_t)r * NQKV + NKV + Dn + c * 4;
    } else {
        int j = i - XT4 - WQ4 - 2 * WK4;
        src = wo + (size_t)j * 4;
        dst = g_woh; doff = (size_t)j * 4;
    }
    float4 v = *(const float4*)src;
    __half2 a = __floats2half2_rn(v.x, v.y);
    __half2 b = __floats2half2_rn(v.z, v.w);
    *(uint32_t*)(dst + doff)     = *reinterpret_cast<uint32_t*>(&a);
    *(uint32_t*)(dst + doff + 2) = *reinterpret_cast<uint32_t*>(&b);
}

__global__ void convert_all(const float* __restrict__ x,
                            const float* __restrict__ wq,
                            const float* __restrict__ wk,
                            const float* __restrict__ wv,
                            const float* __restrict__ wo,
                            const int* __restrict__ pos_ids)
{
    int i0 = blockIdx.x * blockDim.x + threadIdx.x;
    if (i0 >= CVT_THREADS) return;
    if (i0 < RT) {
        int l = i0 >> 5, j = i0 & 31;
        float pos = (float)pos_ids[l];
        float inv = expf(-logf(10000.0f) * ((float)j / 32.0f));
        float ang = pos * inv;
        g_rope[i0] = make_float2(cosf(ang), sinf(ang));
        return;
    }
    int base = i0 - RT;
#pragma unroll
    for (int rep = 0; rep < CVT_REP; rep++) {
        int i = base + rep * CVT4S;
        if (i < TOT4) cvt_one(i, x, wq, wk, wv, wo);
    }
}

// ---------------------------------------------------------------------------
// Pure fp16 GEMM, tile (TM x 128), K-tile 64, 3-stage cp.async.
// TM=128 (2 CTA/SM) or TM=64 (3 CTA/SM, finer work quantization).
// EPI=0: plain fp32 C store. EPI=1 (TM=128 only): fused QKV epilogue.
// ---------------------------------------------------------------------------
template <int TM, int EPI>
__global__ __launch_bounds__(256, (TM == 128) ? 2 : 3) void gemm_fp16_kernel(
    const __half* __restrict__ Ah, const __half* __restrict__ Bh,
    float* __restrict__ C, int Ndim, int Kdim)
{
    constexpr int MT = TM / 32;              // m16-frags per warp
    constexpr int A_BYTES = TM * 128;
    constexpr int STG = A_BYTES + 16384;

    extern __shared__ char smraw[];
    const uint32_t smb = smem_u32(smraw);
    const int tid = threadIdx.x;
    const int wid = tid >> 5;
    const int lane = tid & 31;
    const int bm = blockIdx.y * TM;
    const int bn = blockIdx.x * 128;
    const int wm = wid >> 2;
    const int wn = wid & 3;

    float c[MT][4][4];
#pragma unroll
    for (int mt = 0; mt < MT; mt++)
#pragma unroll
        for (int nt = 0; nt < 4; nt++)
#pragma unroll
            for (int r = 0; r < 4; r++) c[mt][nt][r] = 0.0f;

    const int nk = Kdim / 64;

#define LOAD_TILE(s, k0) do { \
        uint32_t baseA = smb + (s) * STG; \
        uint32_t baseB = baseA + A_BYTES; \
        const int ca = tid & 7; \
        _Pragma("unroll") \
        for (int it = 0; it < TM / 32; it++) { \
            int row = (tid >> 3) + it * 32; \
            const __half* src = Ah + (size_t)(bm + row) * Kdim + (k0) + ca * 8; \
            CP_ASYNC16(baseA + row * 128 + ((ca ^ (row & 7)) << 4), src); \
        } \
        const int cb = tid & 15; \
        _Pragma("unroll") \
        for (int it = 0; it < 4; it++) { \
            int kr = (tid >> 4) + it * 16; \
            uint32_t off = kr * 256 + ((cb ^ (kr & 7)) << 4); \
            CP_ASYNC16(baseB + off, Bh + (size_t)((k0) + kr) * Ndim + bn + cb * 8); \
        } \
    } while (0)

    LOAD_TILE(0, 0);
    CP_COMMIT();
    LOAD_TILE(1, 64);
    CP_COMMIT();

    const int a_row_l = (lane & 15);
    const int a_inner = (lane >> 4) & 1;
    const int b_krow_l = ((lane >> 3) & 1) * 8 + (lane & 7);
    const int b_nch = (lane >> 4) & 1;

    for (int i = 0; i < nk; i++) {
        CP_WAIT1();
        __syncthreads();
        if (i + 2 < nk) {
            int s = (i + 2) % 3;
            LOAD_TILE(s, (i + 2) * 64);
        }
        CP_COMMIT();

        const int buf = i % 3;
        const uint32_t smA = smb + buf * STG;
        const uint32_t smB = smA + A_BYTES;

#pragma unroll
        for (int kk = 0; kk < 4; kk++) {
            uint32_t ah[MT][4];
#pragma unroll
            for (int mt = 0; mt < MT; mt++) {
                int row = wm * (TM / 2) + mt * 16 + a_row_l;
                int lch = kk * 2 + a_inner;
                uint32_t off = smA + row * 128 + ((lch ^ (row & 7)) << 4);
                LDSM4(ah[mt], off);
            }
            uint32_t bh[4][2];
#pragma unroll
            for (int p = 0; p < 2; p++) {
                int kr = kk * 16 + b_krow_l;
                int nchunk = wn * 4 + p * 2 + b_nch;
                uint32_t off = kr * 256 + ((nchunk ^ (kr & 7)) << 4);
                uint32_t r[4];
                LDSM4T(r, smB + off);
                bh[2 * p][0] = r[0]; bh[2 * p][1] = r[1];
                bh[2 * p + 1][0] = r[2]; bh[2 * p + 1][1] = r[3];
            }
#pragma unroll
            for (int mt = 0; mt < MT; mt++)
#pragma unroll
                for (int nt = 0; nt < 4; nt++)
                    MMA_FP16(c[mt][nt], ah[mt], bh[nt][0], bh[nt][1]);
        }
    }

    const int g = lane >> 2;
    const int cc2 = lane & 3;

    if (EPI == 0) {
#pragma unroll
        for (int mt = 0; mt < MT; mt++) {
            int row0 = bm + wm * (TM / 2) + mt * 16 + g;
#pragma unroll
            for (int nt = 0; nt < 4; nt++) {
                int col = bn + wn * 32 + nt * 8 + 2 * cc2;
                *(float2*)&C[(size_t)row0 * Ndim + col] =
                    make_float2(c[mt][nt][0], c[mt][nt][1]);
                *(float2*)&C[(size_t)(row0 + 8) * Ndim + col] =
                    make_float2(c[mt][nt][2], c[mt][nt][3]);
            }
        }
    } else {
#pragma unroll
        for (int mt = 0; mt < MT; mt++) {
            int r0 = bm + wm * (TM / 2) + mt * 16 + g;
            int r1 = r0 + 8;
            int b0 = r0 / Ln, l0 = r0 - b0 * Ln;
            int b1 = r1 / Ln, l1 = r1 - b1 * Ln;
#pragma unroll
            for (int nt = 0; nt < 4; nt++) {
                int col = bn + wn * 32 + nt * 8 + 2 * cc2;
                if (bn < Dn) {
                    // Q: rope + pre-scale by QSCALE + fp16, row-major
                    int j = (col & 63) >> 1;
                    float2 cs0 = g_rope[l0 * 32 + j];
                    float2 cs1 = g_rope[l1 * 32 + j];
                    float y00 = (c[mt][nt][0] * cs0.x - c[mt][nt][1] * cs0.y) * QSCALE;
                    float y01 = (c[mt][nt][0] * cs0.y + c[mt][nt][1] * cs0.x) * QSCALE;
                    float y10 = (c[mt][nt][2] * cs1.x - c[mt][nt][3] * cs1.y) * QSCALE;
                    float y11 = (c[mt][nt][2] * cs1.y + c[mt][nt][3] * cs1.x) * QSCALE;
                    __half2 h0 = __floats2half2_rn(y00, y01);
                    __half2 h1 = __floats2half2_rn(y10, y11);
                    *(uint32_t*)(g_qh + (size_t)r0 * Dn + col) = *reinterpret_cast<uint32_t*>(&h0);
                    *(uint32_t*)(g_qh + (size_t)r1 * Dn + col) = *reinterpret_cast<uint32_t*>(&h1);
                } else if (bn < Dn + NKV) {
                    int coln = col - Dn;
                    int kvh = coln >> 6;
                    int j = (coln & 63) >> 1;
                    float2 cs0 = g_rope[l0 * 32 + j];
                    float2 cs1 = g_rope[l1 * 32 + j];
                    float y00 = c[mt][nt][0] * cs0.x - c[mt][nt][1] * cs0.y;
                    float y01 = c[mt][nt][0] * cs0.y + c[mt][nt][1] * cs0.x;
                    float y10 = c[mt][nt][2] * cs1.x - c[mt][nt][3] * cs1.y;
                    float y11 = c[mt][nt][2] * cs1.y + c[mt][nt][3] * cs1.x;
                    size_t base0 = ((size_t)(b0 * HKVn + kvh) * HDn + 2 * j) * Ln + l0;
                    size_t base1 = ((size_t)(b1 * HKVn + kvh) * HDn + 2 * j) * Ln + l1;
                    g_kth[base0]      = __float2half_rn(y00);
                    g_kth[base0 + Ln] = __float2half_rn(y01);
                    g_kth[base1]      = __float2half_rn(y10);
                    g_kth[base1 + Ln] = __float2half_rn(y11);
                } else {
                    int coln = col - Dn - NKV;
                    __half2 h0 = __floats2half2_rn(c[mt][nt][0], c[mt][nt][1]);
                    __half2 h1 = __floats2half2_rn(c[mt][nt][2], c[mt][nt][3]);
                    *(uint32_t*)(g_vh + (size_t)r0 * NKV + coln) = *reinterpret_cast<uint32_t*>(&h0);
                    *(uint32_t*)(g_vh + (size_t)r1 * NKV + coln) = *reinterpret_cast<uint32_t*>(&h1);
                }
            }
        }
    }
#undef LOAD_TILE
}

#define GEMM_SMEM_128 (3 * (128 * 128 + 16384))
#define GEMM_SMEM_64  (3 * (64 * 128 + 16384))

// ---------------------------------------------------------------------------
// Tensor-core flash attention (unchanged from R15).
// SMEM: Q 8KB + 2 x (K 8KB | V 8KB) = 40KB.
// ---------------------------------------------------------------------------
#define ATT_SMEM_BYTES (8192 + 2 * 16384)

__global__ __launch_bounds__(128, 4) void attn_kernel()
{
    extern __shared__ char smraw[];
    const uint32_t smb = smem_u32(smraw);
    const int tid = threadIdx.x;
    const int wid = tid >> 5;
    const int lane = tid & 31;
    const int qt = (gridDim.x - 1) - blockIdx.x;   // LPT: heavy tiles first
    const int h = blockIdx.y, b = blockIdx.z;
    const int l0 = qt * 64;
    const int kh = h >> 2;

    const uint32_t QH = smb;

#pragma unroll
    for (int it = 0; it < 4; it++) {
        int idx = tid + it * 128;
        int row = idx >> 3, c = idx & 7;
        uint32_t off = row * 128 + ((c ^ (row & 7)) << 4);
        size_t g = (size_t)(b * Ln + l0 + row) * Dn + h * HDn + c * 8;
        CP_ASYNC16(QH + off, g_qh + g);
    }

#define LOAD_KV(p, m0_) do { \
        uint32_t KB = smb + 8192 + (p) * 16384; \
        _Pragma("unroll") \
        for (int it = 0; it < 4; it++) { \
            int idx = tid + it * 128; \
            int row = idx >> 3, c = idx & 7; \
            uint32_t off = row * 128 + (uint32_t)((c ^ (row & 7)) << 4); \
            size_t gk = ((size_t)(b * HKVn + kh) * HDn + row) * Ln + (m0_) + c * 8; \
            size_t gv = (size_t)(b * Ln + (m0_) + row) * NKV + kh * HDn + c * 8; \
            CP_ASYNC16(KB + off,        g_kth + gk); \
            CP_ASYNC16(KB + 8192 + off, g_vh + gv); \
        } \
    } while (0)

    int maxm = ((l0 + 63) / TPF) * TPF + TPF - 1;
    if (maxm > Ln - 1) maxm = Ln - 1;
    const int nkt = maxm / 64 + 1;

    LOAD_KV(0, 0);
    CP_COMMIT();

    const int q4 = lane & 3;
    const int rr = lane >> 2;
    const int aRow = wid * 16 + (lane & 15);
    const int aSel = (lane >> 4) & 1;
    const int bKr = ((lane >> 3) & 1) * 8 + (lane & 7);
    const int bNch = (lane >> 4) & 1;
    const int grow0 = l0 + wid * 16 + rr;
    const int grow1 = grow0 + 8;
    const int rowmax0 = (grow0 / TPF) * TPF + TPF - 1;
    const int rowmax1 = (grow1 / TPF) * TPF + TPF - 1;
    const int l0fid = l0 / TPF;

    uint32_t bBase[4];
#pragma unroll
    for (int np = 0; np < 4; np++)
        bBase[np] = (uint32_t)(bKr * 128 + (((np * 2 + bNch) ^ (bKr & 7)) << 4));
    uint32_t aBase[4];
#pragma unroll
    for (int kb = 0; kb < 4; kb++)
        aBase[kb] = (uint32_t)(aRow * 128 + (((kb * 2 + aSel) ^ (aRow & 7)) << 4));

    const uint32_t onesf = (lane < 4) ? 0x3C003C00u : 0u;

    float o[8][4];
#pragma unroll
    for (int nt = 0; nt < 8; nt++)
#pragma unroll
        for (int r = 0; r < 4; r++) o[nt][r] = 0.0f;
    float ssum[4] = {0.0f, 0.0f, 0.0f, 0.0f};

    for (int i = 0; i < nkt; i++) {
        if (i + 1 < nkt) {
            LOAD_KV((i + 1) & 1, (i + 1) * 64);
            CP_COMMIT();
            CP_WAIT1();
        } else {
            CP_WAIT0();
        }
        __syncthreads();

        const uint32_t KB = smb + 8192 + (i & 1) * 16384;
        const uint32_t KHs = KB, VHs = KB + 8192;
        const int m0 = i * 64;

        float s[8][4];
#pragma unroll
        for (int nt = 0; nt < 8; nt++)
#pragma unroll
            for (int r = 0; r < 4; r++) s[nt][r] = 0.0f;

#pragma unroll
        for (int kb = 0; kb < 4; kb++) {
            uint32_t aH[4];
            LDSM4(aH, QH + aBase[kb]);
            const uint32_t kOff = KHs + (uint32_t)(kb * 2048);
#pragma unroll
            for (int np = 0; np < 4; np++) {
                uint32_t kf[4];
                LDSM4T(kf, kOff + bBase[np]);
                MMA_FP16(s[2 * np],     aH, kf[0], kf[1]);
                MMA_FP16(s[2 * np + 1], aH, kf[2], kf[3]);
            }
        }

        const bool full = ((m0 + 63) / TPF) <= l0fid;
        if (!full) {
#pragma unroll
            for (int nt = 0; nt < 8; nt++) {
                int colb = m0 + nt * 8 + 2 * q4;
                if (colb > rowmax0)     s[nt][0] = -30000.0f;
                if (colb + 1 > rowmax0) s[nt][1] = -30000.0f;
                if (colb > rowmax1)     s[nt][2] = -30000.0f;
                if (colb + 1 > rowmax1) s[nt][3] = -30000.0f;
            }
        }

#pragma unroll
        for (int kb = 0; kb < 4; kb++) {
            uint32_t ph[4];
            {
                __half2 t0 = __floats2half2_rn(s[2 * kb][0],     s[2 * kb][1]);
                __half2 t1 = __floats2half2_rn(s[2 * kb][2],     s[2 * kb][3]);
                __half2 t2 = __floats2half2_rn(s[2 * kb + 1][0], s[2 * kb + 1][1]);
                __half2 t3 = __floats2half2_rn(s[2 * kb + 1][2], s[2 * kb + 1][3]);
                ph[0] = ex2h2(*reinterpret_cast<uint32_t*>(&t0));
                ph[1] = ex2h2(*reinterpret_cast<uint32_t*>(&t1));
                ph[2] = ex2h2(*reinterpret_cast<uint32_t*>(&t2));
                ph[3] = ex2h2(*reinterpret_cast<uint32_t*>(&t3));
            }
            MMA_FP16(ssum, ph, onesf, onesf);
            const uint32_t vOff = VHs + (uint32_t)(kb * 2048);
#pragma unroll
            for (int np = 0; np < 4; np++) {
                uint32_t vf[4];
                LDSM4T(vf, vOff + bBase[np]);
                MMA_FP16(o[2 * np],     ph, vf[0], vf[1]);
                MMA_FP16(o[2 * np + 1], ph, vf[2], vf[3]);
            }
        }
        __syncthreads();
    }

    float rs0 = __shfl_sync(0xffffffffu, ssum[0], lane & ~3);
    float rs1 = __shfl_sync(0xffffffffu, ssum[2], lane & ~3);
    float inv0 = 1.0f / rs0, inv1 = 1.0f / rs1;
#pragma unroll
    for (int nt = 0; nt < 8; nt++) {
        size_t a0 = (size_t)(b * Ln + grow0) * Dn + h * HDn + nt * 8 + 2 * q4;
        __half2 h0 = __floats2half2_rn(o[nt][0] * inv0, o[nt][1] * inv0);
        *(uint32_t*)(g_ah + a0) = *reinterpret_cast<uint32_t*>(&h0);
        size_t a1 = (size_t)(b * Ln + grow1) * Dn + h * HDn + nt * 8 + 2 * q4;
        __half2 h1 = __floats2half2_rn(o[nt][2] * inv1, o[nt][3] * inv1);
        *(uint32_t*)(g_ah + a1) = *reinterpret_cast<uint32_t*>(&h1);
    }
#undef LOAD_KV
}

// ---------------------------------------------------------------------------
// Launch
// ---------------------------------------------------------------------------
extern "C" void kernel_launch(void* const* d_in, const int* in_sizes, int n_in,
                              void* d_out, int out_size)
{
    const float* x   = (const float*)d_in[0];
    const float* wq  = (const float*)d_in[1];
    const float* wk  = (const float*)d_in[2];
    const float* wv  = (const float*)d_in[3];
    const float* wo  = (const float*)d_in[4];
    const int*   pos = (const int*)d_in[5];
    float* out = (float*)d_out;

    __half *xh, *wqkvh, *woh, *ah;
    cudaGetSymbolAddress((void**)&xh,    g_xh);
    cudaGetSymbolAddress((void**)&wqkvh, g_wqkvh);
    cudaGetSymbolAddress((void**)&woh,   g_woh);
    cudaGetSymbolAddress((void**)&ah,    g_ah);

    cudaFuncSetAttribute((const void*)gemm_fp16_kernel<128, 1>,
                         cudaFuncAttributeMaxDynamicSharedMemorySize,
                         GEMM_SMEM_128);
    cudaFuncSetAttribute((const void*)gemm_fp16_kernel<64, 0>,
                         cudaFuncAttributeMaxDynamicSharedMemorySize,
                         GEMM_SMEM_64);
    cudaFuncSetAttribute((const void*)attn_kernel,
                         cudaFuncAttributeMaxDynamicSharedMemorySize,
                         ATT_SMEM_BYTES);

    // One fused convert (rope table + x + all weights), 4 float4/thread
    convert_all<<<(CVT_THREADS + 255) / 256, 256>>>(x, wq, wk, wv, wo, pos);

    // Fused QKV GEMM (128-tile) with rope/transpose/fp16 epilogue
    dim3 gqkv(NQKV / 128, MROWS / 128);    // 24 x 28
    gemm_fp16_kernel<128, 1><<<gqkv, 256, GEMM_SMEM_128>>>(xh, wqkvh, out /*unused*/, NQKV, Dn);

    dim3 ga(Ln / 64, HQn, Bn);
    attn_kernel<<<ga, 128, ATT_SMEM_BYTES>>>();

    // wo GEMM: M64 tiles for finer per-SM work quantization
    dim3 go(Dn / 128, MROWS / 64);         // 16 x 56
    gemm_fp16_kernel<64, 0><<<go, 256, GEMM_SMEM_64>>>(ah, woh, out, Dn, Dn);
}

// round 17
// speedup vs baseline: 1.0178x; 1.0178x over previous
#include <cuda_runtime.h>
#include <cuda_fp16.h>
#include <cstdint>

// Problem constants
#define Bn 4
#define Ln 896
#define Dn 2048
#define HQn 32
#define HKVn 8
#define HDn 64
#define TPF 7
#define MROWS (Bn * Ln)      // 3584
#define NKV (HKVn * HDn)     // 512
#define NQKV (Dn + 2 * NKV)  // 3072
#define LOG2E 1.4426950408889634f
#define QSCALE (0.125f * LOG2E)   // folded into Q at the QKV epilogue

// fp16 operand buffers (no allocation allowed -> device globals)
__device__ __half g_xh[MROWS * Dn];                       // x
__device__ __half g_wqkvh[Dn * NQKV];                     // packed weights
__device__ __half g_woh[Dn * Dn];                         // wo
__device__ __half g_qh[MROWS * Dn];                       // rope'd Q (pre-scaled by QSCALE)
__device__ __half g_kth[MROWS * NKV];                     // rope'd K^T [b][kvh][d][L]
__device__ __half g_vh[MROWS * NKV];                      // V
__device__ __half g_ah[MROWS * Dn];                       // attention out
__device__ float2 g_rope[Ln * 32];                        // (cos, sin) per (l, j)

__device__ __forceinline__ uint32_t smem_u32(const void* p) {
    uint32_t a;
    asm("{ .reg .u64 t; cvta.to.shared.u64 t, %1; cvt.u32.u64 %0, t; }"
        : "=r"(a) : "l"(p));
    return a;
}

#define CP_ASYNC16(dst, src) \
    asm volatile("cp.async.cg.shared.global [%0], [%1], 16;" :: "r"(dst), "l"(src))
#define CP_COMMIT() asm volatile("cp.async.commit_group;" ::: "memory")
#define CP_WAIT1()  asm volatile("cp.async.wait_group 1;" ::: "memory")
#define CP_WAIT0()  asm volatile("cp.async.wait_group 0;" ::: "memory")

#define MMA_FP16(cc, a, b0, b1) \
    asm volatile( \
        "mma.sync.aligned.m16n8k16.row.col.f32.f16.f16.f32 " \
        "{%0,%1,%2,%3}, {%4,%5,%6,%7}, {%8,%9}, {%0,%1,%2,%3};" \
        : "+f"((cc)[0]), "+f"((cc)[1]), "+f"((cc)[2]), "+f"((cc)[3]) \
        : "r"((a)[0]), "r"((a)[1]), "r"((a)[2]), "r"((a)[3]), \
          "r"(b0), "r"(b1))

#define LDSM4(r, addr) \
    asm volatile("ldmatrix.sync.aligned.m8n8.x4.shared.b16 {%0,%1,%2,%3}, [%4];" \
        : "=r"((r)[0]), "=r"((r)[1]), "=r"((r)[2]), "=r"((r)[3]) : "r"(addr))
#define LDSM4T(r, addr) \
    asm volatile("ldmatrix.sync.aligned.m8n8.x4.trans.shared.b16 {%0,%1,%2,%3}, [%4];" \
        : "=r"((r)[0]), "=r"((r)[1]), "=r"((r)[2]), "=r"((r)[3]) : "r"(addr))

// Hardware exp2 on two fp16 lanes at once (MUFU pipe).
__device__ __forceinline__ uint32_t ex2h2(uint32_t x) {
    uint32_t r;
    asm("ex2.approx.f16x2 %0, %1;" : "=r"(r) : "r"(x));
    return r;
}

// ---------------------------------------------------------------------------
// Fused convert + rope-table kernel: x + [wq|wk|wv]. (wo conversion is
// hidden inside the QKV GEMM main loop.) Grid-strided 4 float4/thread.
// ---------------------------------------------------------------------------
#define RT    (Ln * 32)
#define XT4   (MROWS * Dn / 4)
#define WQ4   (Dn * Dn / 4)
#define WK4   (Dn * NKV / 4)
#define TOT4  (XT4 + WQ4 + 2 * WK4)
#define CVT_REP 4
#define CVT4S ((TOT4 + CVT_REP - 1) / CVT_REP)
#define CVT_THREADS (RT + CVT4S)

__device__ __forceinline__ void cvt_one(int i,
    const float* __restrict__ x, const float* __restrict__ wq,
    const float* __restrict__ wk, const float* __restrict__ wv)
{
    const float* src;
    __half* dst;
    size_t doff;
    if (i < XT4) {
        src = x + (size_t)i * 4;
        dst = g_xh; doff = (size_t)i * 4;
    } else if (i < XT4 + WQ4) {
        int j = i - XT4;
        int r = j / (Dn / 4), c = j - r * (Dn / 4);
        src = wq + ((size_t)r * Dn + c * 4);
        dst = g_wqkvh; doff = (size_t)r * NQKV + c * 4;
    } else if (i < XT4 + WQ4 + WK4) {
        int j = i - XT4 - WQ4;
        int r = j / (NKV / 4), c = j - r * (NKV / 4);
        src = wk + ((size_t)r * NKV + c * 4);
        dst = g_wqkvh; doff = (size_t)r * NQKV + Dn + c * 4;
    } else {
        int j = i - XT4 - WQ4 - WK4;
        int r = j / (NKV / 4), c = j - r * (NKV / 4);
        src = wv + ((size_t)r * NKV + c * 4);
        dst = g_wqkvh; doff = (size_t)r * NQKV + NKV + Dn + c * 4;
    }
    float4 v = *(const float4*)src;
    __half2 a = __floats2half2_rn(v.x, v.y);
    __half2 b = __floats2half2_rn(v.z, v.w);
    *(uint32_t*)(dst + doff)     = *reinterpret_cast<uint32_t*>(&a);
    *(uint32_t*)(dst + doff + 2) = *reinterpret_cast<uint32_t*>(&b);
}

__global__ void convert_all(const float* __restrict__ x,
                            const float* __restrict__ wq,
                            const float* __restrict__ wk,
                            const float* __restrict__ wv,
                            const int* __restrict__ pos_ids)
{
    int i0 = blockIdx.x * blockDim.x + threadIdx.x;
    if (i0 >= CVT_THREADS) return;
    if (i0 < RT) {
        int l = i0 >> 5, j = i0 & 31;
        float pos = (float)pos_ids[l];
        float inv = expf(-logf(10000.0f) * ((float)j / 32.0f));
        float ang = pos * inv;
        g_rope[i0] = make_float2(cosf(ang), sinf(ang));
        return;
    }
    int base = i0 - RT;
#pragma unroll
    for (int rep = 0; rep < CVT_REP; rep++) {
        int i = base + rep * CVT4S;
        if (i < TOT4) cvt_one(i, x, wq, wk, wv);
    }
}

// ---------------------------------------------------------------------------
// Pure fp16 GEMM: 128x128 CTA, K-tile 64, 3-stage cp.async, 2 CTA/SM.
// EPI=0: plain fp32 C store.
// EPI=1: fused QKV epilogue (rope/transpose/fp16, Q pre-scaled) AND hides
//        the wo fp32->fp16 conversion in the main loop (idle DRAM slots).
// ---------------------------------------------------------------------------
#define STAGE_BYTES (16384 + 16384)
#define GEMM_SMEM_BYTES (3 * STAGE_BYTES)

template <int EPI>
__global__ __launch_bounds__(256, 2) void gemm_fp16_kernel(
    const __half* __restrict__ Ah, const __half* __restrict__ Bh,
    float* __restrict__ C, const float* __restrict__ Wsrc,
    int Ndim, int Kdim)
{
    extern __shared__ char smraw[];
    const uint32_t smb = smem_u32(smraw);
    const int tid = threadIdx.x;
    const int wid = tid >> 5;
    const int lane = tid & 31;
    const int bm = blockIdx.y * 128;
    const int bn = blockIdx.x * 128;
    const int wm = wid >> 2;
    const int wn = wid & 3;

    float c[4][4][4];
#pragma unroll
    for (int mt = 0; mt < 4; mt++)
#pragma unroll
        for (int nt = 0; nt < 4; nt++)
#pragma unroll
            for (int r = 0; r < 4; r++) c[mt][nt][r] = 0.0f;

    const int nk = Kdim / 64;
    // Hidden wo conversion bookkeeping (EPI=1): 7 chunks/thread across iters.
    const int cid = blockIdx.y * gridDim.x + blockIdx.x;
    const int wbase = cid * (7 * 256) + tid;

#define LOAD_TILE(s, k0) do { \
        uint32_t baseA = smb + (s) * STAGE_BYTES; \
        uint32_t baseB = baseA + 16384; \
        const int ca = tid & 7; \
        _Pragma("unroll") \
        for (int it = 0; it < 4; it++) { \
            int row = (tid >> 3) + it * 32; \
            const __half* src = Ah + (size_t)(bm + row) * Kdim + (k0) + ca * 8; \
            CP_ASYNC16(baseA + row * 128 + ((ca ^ (row & 7)) << 4), src); \
        } \
        const int cb = tid & 15; \
        _Pragma("unroll") \
        for (int it = 0; it < 4; it++) { \
            int kr = (tid >> 4) + it * 16; \
            uint32_t off = kr * 256 + ((cb ^ (kr & 7)) << 4); \
            CP_ASYNC16(baseB + off, Bh + (size_t)((k0) + kr) * Ndim + bn + cb * 8); \
        } \
    } while (0)

    LOAD_TILE(0, 0);
    CP_COMMIT();
    LOAD_TILE(1, 64);
    CP_COMMIT();

    const int a_row_l = (lane & 15);
    const int a_inner = (lane >> 4) & 1;
    const int b_krow_l = ((lane >> 3) & 1) * 8 + (lane & 7);
    const int b_nch = (lane >> 4) & 1;

    for (int i = 0; i < nk; i++) {
        CP_WAIT1();
        __syncthreads();
        if (i + 2 < nk) {
            int s = (i + 2) % 3;
            LOAD_TILE(s, (i + 2) * 64);
        }
        CP_COMMIT();

        // Hidden wo conversion: one coalesced float4 per thread, iters 0-6.
        if (EPI == 1 && i < 7) {
            int idx = wbase + i * 256;
            if (idx < Dn * Dn / 4) {
                float4 v = ((const float4*)Wsrc)[idx];
                __half2 a = __floats2half2_rn(v.x, v.y);
                __half2 b2 = __floats2half2_rn(v.z, v.w);
                *(uint32_t*)(g_woh + (size_t)idx * 4)     = *reinterpret_cast<uint32_t*>(&a);
                *(uint32_t*)(g_woh + (size_t)idx * 4 + 2) = *reinterpret_cast<uint32_t*>(&b2);
            }
        }

        const int buf = i % 3;
        const uint32_t smA = smb + buf * STAGE_BYTES;
        const uint32_t smB = smA + 16384;

#pragma unroll
        for (int kk = 0; kk < 4; kk++) {
            uint32_t ah[4][4];
#pragma unroll
            for (int mt = 0; mt < 4; mt++) {
                int row = wm * 64 + mt * 16 + a_row_l;
                int lch = kk * 2 + a_inner;
                uint32_t off = smA + row * 128 + ((lch ^ (row & 7)) << 4);
                LDSM4(ah[mt], off);
            }
            uint32_t bh[4][2];
#pragma unroll
            for (int p = 0; p < 2; p++) {
                int kr = kk * 16 + b_krow_l;
                int nchunk = wn * 4 + p * 2 + b_nch;
                uint32_t off = kr * 256 + ((nchunk ^ (kr & 7)) << 4);
                uint32_t r[4];
                LDSM4T(r, smB + off);
                bh[2 * p][0] = r[0]; bh[2 * p][1] = r[1];
                bh[2 * p + 1][0] = r[2]; bh[2 * p + 1][1] = r[3];
            }
#pragma unroll
            for (int mt = 0; mt < 4; mt++)
#pragma unroll
                for (int nt = 0; nt < 4; nt++)
                    MMA_FP16(c[mt][nt], ah[mt], bh[nt][0], bh[nt][1]);
        }
    }

    const int g = lane >> 2;
    const int cc2 = lane & 3;

    if (EPI == 0) {
#pragma unroll
        for (int mt = 0; mt < 4; mt++) {
            int row0 = bm + wm * 64 + mt * 16 + g;
#pragma unroll
            for (int nt = 0; nt < 4; nt++) {
                int col = bn + wn * 32 + nt * 8 + 2 * cc2;
                *(float2*)&C[(size_t)row0 * Ndim + col] =
                    make_float2(c[mt][nt][0], c[mt][nt][1]);
                *(float2*)&C[(size_t)(row0 + 8) * Ndim + col] =
                    make_float2(c[mt][nt][2], c[mt][nt][3]);
            }
        }
    } else {
#pragma unroll
        for (int mt = 0; mt < 4; mt++) {
            int r0 = bm + wm * 64 + mt * 16 + g;
            int r1 = r0 + 8;
            int b0 = r0 / Ln, l0 = r0 - b0 * Ln;
            int b1 = r1 / Ln, l1 = r1 - b1 * Ln;
#pragma unroll
            for (int nt = 0; nt < 4; nt++) {
                int col = bn + wn * 32 + nt * 8 + 2 * cc2;
                if (bn < Dn) {
                    // Q: rope + pre-scale by QSCALE + fp16, row-major
                    int j = (col & 63) >> 1;
                    float2 cs0 = g_rope[l0 * 32 + j];
                    float2 cs1 = g_rope[l1 * 32 + j];
                    float y00 = (c[mt][nt][0] * cs0.x - c[mt][nt][1] * cs0.y) * QSCALE;
                    float y01 = (c[mt][nt][0] * cs0.y + c[mt][nt][1] * cs0.x) * QSCALE;
                    float y10 = (c[mt][nt][2] * cs1.x - c[mt][nt][3] * cs1.y) * QSCALE;
                    float y11 = (c[mt][nt][2] * cs1.y + c[mt][nt][3] * cs1.x) * QSCALE;
                    __half2 h0 = __floats2half2_rn(y00, y01);
                    __half2 h1 = __floats2half2_rn(y10, y11);
                    *(uint32_t*)(g_qh + (size_t)r0 * Dn + col) = *reinterpret_cast<uint32_t*>(&h0);
                    *(uint32_t*)(g_qh + (size_t)r1 * Dn + col) = *reinterpret_cast<uint32_t*>(&h1);
                } else if (bn < Dn + NKV) {
                    int coln = col - Dn;
                    int kvh = coln >> 6;
                    int j = (coln & 63) >> 1;
                    float2 cs0 = g_rope[l0 * 32 + j];
                    float2 cs1 = g_rope[l1 * 32 + j];
                    float y00 = c[mt][nt][0] * cs0.x - c[mt][nt][1] * cs0.y;
                    float y01 = c[mt][nt][0] * cs0.y + c[mt][nt][1] * cs0.x;
                    float y10 = c[mt][nt][2] * cs1.x - c[mt][nt][3] * cs1.y;
                    float y11 = c[mt][nt][2] * cs1.y + c[mt][nt][3] * cs1.x;
                    size_t base0 = ((size_t)(b0 * HKVn + kvh) * HDn + 2 * j) * Ln + l0;
                    size_t base1 = ((size_t)(b1 * HKVn + kvh) * HDn + 2 * j) * Ln + l1;
                    g_kth[base0]      = __float2half_rn(y00);
                    g_kth[base0 + Ln] = __float2half_rn(y01);
                    g_kth[base1]      = __float2half_rn(y10);
                    g_kth[base1 + Ln] = __float2half_rn(y11);
                } else {
                    int coln = col - Dn - NKV;
                    __half2 h0 = __floats2half2_rn(c[mt][nt][0], c[mt][nt][1]);
                    __half2 h1 = __floats2half2_rn(c[mt][nt][2], c[mt][nt][3]);
                    *(uint32_t*)(g_vh + (size_t)r0 * NKV + coln) = *reinterpret_cast<uint32_t*>(&h0);
                    *(uint32_t*)(g_vh + (size_t)r1 * NKV + coln) = *reinterpret_cast<uint32_t*>(&h1);
                }
            }
        }
    }
#undef LOAD_TILE
}

// ---------------------------------------------------------------------------
// Tensor-core flash attention (unchanged from R15).
// SMEM: Q 8KB + 2 x (K 8KB | V 8KB) = 40KB.
// ---------------------------------------------------------------------------
#define ATT_SMEM_BYTES (8192 + 2 * 16384)

__global__ __launch_bounds__(128, 4) void attn_kernel()
{
    extern __shared__ char smraw[];
    const uint32_t smb = smem_u32(smraw);
    const int tid = threadIdx.x;
    const int wid = tid >> 5;
    const int lane = tid & 31;
    const int qt = (gridDim.x - 1) - blockIdx.x;   // LPT: heavy tiles first
    const int h = blockIdx.y, b = blockIdx.z;
    const int l0 = qt * 64;
    const int kh = h >> 2;

    const uint32_t QH = smb;

#pragma unroll
    for (int it = 0; it < 4; it++) {
        int idx = tid + it * 128;
        int row = idx >> 3, c = idx & 7;
        uint32_t off = row * 128 + ((c ^ (row & 7)) << 4);
        size_t g = (size_t)(b * Ln + l0 + row) * Dn + h * HDn + c * 8;
        CP_ASYNC16(QH + off, g_qh + g);
    }

#define LOAD_KV(p, m0_) do { \
        uint32_t KB = smb + 8192 + (p) * 16384; \
        _Pragma("unroll") \
        for (int it = 0; it < 4; it++) { \
            int idx = tid + it * 128; \
            int row = idx >> 3, c = idx & 7; \
            uint32_t off = row * 128 + (uint32_t)((c ^ (row & 7)) << 4); \
            size_t gk = ((size_t)(b * HKVn + kh) * HDn + row) * Ln + (m0_) + c * 8; \
            size_t gv = (size_t)(b * Ln + (m0_) + row) * NKV + kh * HDn + c * 8; \
            CP_ASYNC16(KB + off,        g_kth + gk); \
            CP_ASYNC16(KB + 8192 + off, g_vh + gv); \
        } \
    } while (0)

    int maxm = ((l0 + 63) / TPF) * TPF + TPF - 1;
    if (maxm > Ln - 1) maxm = Ln - 1;
    const int nkt = maxm / 64 + 1;

    LOAD_KV(0, 0);
    CP_COMMIT();

    const int q4 = lane & 3;
    const int rr = lane >> 2;
    const int aRow = wid * 16 + (lane & 15);
    const int aSel = (lane >> 4) & 1;
    const int bKr = ((lane >> 3) & 1) * 8 + (lane & 7);
    const int bNch = (lane >> 4) & 1;
    const int grow0 = l0 + wid * 16 + rr;
    const int grow1 = grow0 + 8;
    const int rowmax0 = (grow0 / TPF) * TPF + TPF - 1;
    const int rowmax1 = (grow1 / TPF) * TPF + TPF - 1;
    const int l0fid = l0 / TPF;

    uint32_t bBase[4];
#pragma unroll
    for (int np = 0; np < 4; np++)
        bBase[np] = (uint32_t)(bKr * 128 + (((np * 2 + bNch) ^ (bKr & 7)) << 4));
    uint32_t aBase[4];
#pragma unroll
    for (int kb = 0; kb < 4; kb++)
        aBase[kb] = (uint32_t)(aRow * 128 + (((kb * 2 + aSel) ^ (aRow & 7)) << 4));

    const uint32_t onesf = (lane < 4) ? 0x3C003C00u : 0u;

    float o[8][4];
#pragma unroll
    for (int nt = 0; nt < 8; nt++)
#pragma unroll
        for (int r = 0; r < 4; r++) o[nt][r] = 0.0f;
    float ssum[4] = {0.0f, 0.0f, 0.0f, 0.0f};

    for (int i = 0; i < nkt; i++) {
        if (i + 1 < nkt) {
            LOAD_KV((i + 1) & 1, (i + 1) * 64);
            CP_COMMIT();
            CP_WAIT1();
        } else {
            CP_WAIT0();
        }
        __syncthreads();

        const uint32_t KB = smb + 8192 + (i & 1) * 16384;
        const uint32_t KHs = KB, VHs = KB + 8192;
        const int m0 = i * 64;

        float s[8][4];
#pragma unroll
        for (int nt = 0; nt < 8; nt++)
#pragma unroll
            for (int r = 0; r < 4; r++) s[nt][r] = 0.0f;

#pragma unroll
        for (int kb = 0; kb < 4; kb++) {
            uint32_t aH[4];
            LDSM4(aH, QH + aBase[kb]);
            const uint32_t kOff = KHs + (uint32_t)(kb * 2048);
#pragma unroll
            for (int np = 0; np < 4; np++) {
                uint32_t kf[4];
                LDSM4T(kf, kOff + bBase[np]);
                MMA_FP16(s[2 * np],     aH, kf[0], kf[1]);
                MMA_FP16(s[2 * np + 1], aH, kf[2], kf[3]);
            }
        }

        const bool full = ((m0 + 63) / TPF) <= l0fid;
        if (!full) {
#pragma unroll
            for (int nt = 0; nt < 8; nt++) {
                int colb = m0 + nt * 8 + 2 * q4;
                if (colb > rowmax0)     s[nt][0] = -30000.0f;
                if (colb + 1 > rowmax0) s[nt][1] = -30000.0f;
                if (colb > rowmax1)     s[nt][2] = -30000.0f;
                if (colb + 1 > rowmax1) s[nt][3] = -30000.0f;
            }
        }

#pragma unroll
        for (int kb = 0; kb < 4; kb++) {
            uint32_t ph[4];
            {
                __half2 t0 = __floats2half2_rn(s[2 * kb][0],     s[2 * kb][1]);
                __half2 t1 = __floats2half2_rn(s[2 * kb][2],     s[2 * kb][3]);
                __half2 t2 = __floats2half2_rn(s[2 * kb + 1][0], s[2 * kb + 1][1]);
                __half2 t3 = __floats2half2_rn(s[2 * kb + 1][2], s[2 * kb + 1][3]);
                ph[0] = ex2h2(*reinterpret_cast<uint32_t*>(&t0));
                ph[1] = ex2h2(*reinterpret_cast<uint32_t*>(&t1));
                ph[2] = ex2h2(*reinterpret_cast<uint32_t*>(&t2));
                ph[3] = ex2h2(*reinterpret_cast<uint32_t*>(&t3));
            }
            MMA_FP16(ssum, ph, onesf, onesf);
            const uint32_t vOff = VHs + (uint32_t)(kb * 2048);
#pragma unroll
            for (int np = 0; np < 4; np++) {
                uint32_t vf[4];
                LDSM4T(vf, vOff + bBase[np]);
                MMA_FP16(o[2 * np],     ph, vf[0], vf[1]);
                MMA_FP16(o[2 * np + 1], ph, vf[2], vf[3]);
            }
        }
        __syncthreads();
    }

    float rs0 = __shfl_sync(0xffffffffu, ssum[0], lane & ~3);
    float rs1 = __shfl_sync(0xffffffffu, ssum[2], lane & ~3);
    float inv0 = 1.0f / rs0, inv1 = 1.0f / rs1;
#pragma unroll
    for (int nt = 0; nt < 8; nt++) {
        size_t a0 = (size_t)(b * Ln + grow0) * Dn + h * HDn + nt * 8 + 2 * q4;
        __half2 h0 = __floats2half2_rn(o[nt][0] * inv0, o[nt][1] * inv0);
        *(uint32_t*)(g_ah + a0) = *reinterpret_cast<uint32_t*>(&h0);
        size_t a1 = (size_t)(b * Ln + grow1) * Dn + h * HDn + nt * 8 + 2 * q4;
        __half2 h1 = __floats2half2_rn(o[nt][2] * inv1, o[nt][3] * inv1);
        *(uint32_t*)(g_ah + a1) = *reinterpret_cast<uint32_t*>(&h1);
    }
#undef LOAD_KV
}

// ---------------------------------------------------------------------------
// Launch
// ---------------------------------------------------------------------------
extern "C" void kernel_launch(void* const* d_in, const int* in_sizes, int n_in,
                              void* d_out, int out_size)
{
    const float* x   = (const float*)d_in[0];
    const float* wq  = (const float*)d_in[1];
    const float* wk  = (const float*)d_in[2];
    const float* wv  = (const float*)d_in[3];
    const float* wo  = (const float*)d_in[4];
    const int*   pos = (const int*)d_in[5];
    float* out = (float*)d_out;

    __half *xh, *wqkvh, *woh, *ah;
    cudaGetSymbolAddress((void**)&xh,    g_xh);
    cudaGetSymbolAddress((void**)&wqkvh, g_wqkvh);
    cudaGetSymbolAddress((void**)&woh,   g_woh);
    cudaGetSymbolAddress((void**)&ah,    g_ah);

    cudaFuncSetAttribute((const void*)gemm_fp16_kernel<1>,
                         cudaFuncAttributeMaxDynamicSharedMemorySize,
                         GEMM_SMEM_BYTES);
    cudaFuncSetAttribute((const void*)gemm_fp16_kernel<0>,
                         cudaFuncAttributeMaxDynamicSharedMemorySize,
                         GEMM_SMEM_BYTES);
    cudaFuncSetAttribute((const void*)attn_kernel,
                         cudaFuncAttributeMaxDynamicSharedMemorySize,
                         ATT_SMEM_BYTES);

    // Fused convert (rope table + x + qkv weights); wo handled in QKV GEMM
    convert_all<<<(CVT_THREADS + 255) / 256, 256>>>(x, wq, wk, wv, pos);

    // Fused QKV GEMM with rope/transpose/fp16 epilogue + hidden wo convert
    dim3 gqkv(NQKV / 128, MROWS / 128);    // 24 x 28
    gemm_fp16_kernel<1><<<gqkv, 256, GEMM_SMEM_BYTES>>>(xh, wqkvh, out /*unused*/, wo, NQKV, Dn);

    dim3 ga(Ln / 64, HQn, Bn);
    attn_kernel<<<ga, 128, ATT_SMEM_BYTES>>>();

    // wo GEMM: proven 128x128 tile
    dim3 go(Dn / 128, MROWS / 128);        // 16 x 28
    gemm_fp16_kernel<0><<<go, 256, GEMM_SMEM_BYTES>>>(ah, woh, out, nullptr, Dn, Dn);
}